// round 2
// baseline (speedup 1.0000x reference)
#include <cuda_runtime.h>
#include <cuda_bf16.h>
#include <math.h>
#include <stddef.h>

#define BB 8
#define LL 2048
#define NNV 512
#define HHV 16
#define CCV 16
#define DDV 64
#define TKV 45
#define BLV (BB*LL)

// ------------------------- scratch (device globals) -------------------------
__device__ float g_normed[LL*NNV];
__device__ float g_simpart[8*NNV*NNV];
__device__ float g_sim[NNV*NNV];
__device__ int   g_topk[NNV*TKV];
__device__ float g_attn[BB*NNV*TKV];
__device__ float g_Q[BB*NNV*HHV];
__device__ float g_K[BB*NNV*HHV];
__device__ float g_imp[BB*NNV];
__device__ float g_summary[BB*NNV];
__device__ float g_ps[BB*16*NNV];
__device__ float g_pq[BB*16*NNV];
__device__ float g_cw[NNV*CCV];
__device__ float g_cwT[CCV*NNV];
__device__ float g_M1[CCV*DDV];
__device__ float g_bb[DDV];
__device__ float g_w2[DDV];
__device__ float g_b2s;
__device__ float g_ct[BB*CCV*DDV];
__device__ float g_ctp[BB*CCV*DDV];
__device__ float g_xcs[(size_t)BLV*CCV];
__device__ float g_ring[(size_t)BLV*NNV];
__device__ float g_c2v[(size_t)BLV*NNV];
__device__ float g_fusedv[(size_t)BLV*NNV];
__device__ float g_h[(size_t)BLV*NNV];

// ------------------------- 1. column stats over batch -----------------------
__global__ void k_colstats(const float* __restrict__ x) {
    int i = blockIdx.x * 256 + threadIdx.x;          // over L*N
    if (i >= LL*NNV) return;
    float v[BB];
#pragma unroll
    for (int b = 0; b < BB; b++) v[b] = x[(size_t)b*LL*NNV + i];
    float s = 0.f;
#pragma unroll
    for (int b = 0; b < BB; b++) s += v[b];
    float mean = s * (1.0f/BB);
    float q = 0.f;
#pragma unroll
    for (int b = 0; b < BB; b++) { float d = v[b]-mean; q += d*d; }
    float stdv = sqrtf(q * (1.0f/(BB-1))) + 1e-5f;
    g_normed[i] = mean / stdv;
}

// ------------------------- 2. sim = normed^T normed (split-K) ---------------
__global__ void k_sim() {
    __shared__ float As[16][64];
    __shared__ float Bs[16][64];
    int tid = threadIdx.x;
    int tx = tid & 15, ty = tid >> 4;
    int m0 = blockIdx.y*64, n0 = blockIdx.x*64, lbase = blockIdx.z*256;
    float acc[4][4];
#pragma unroll
    for (int i = 0; i < 4; i++)
#pragma unroll
        for (int j = 0; j < 4; j++) acc[i][j] = 0.f;
    for (int kc = 0; kc < 256; kc += 16) {
#pragma unroll
        for (int t = 0; t < 4; t++) {
            int fid = tid + t*256;
            int kk = fid >> 6, col = fid & 63;
            As[kk][col] = g_normed[(size_t)(lbase+kc+kk)*NNV + m0 + col];
            Bs[kk][col] = g_normed[(size_t)(lbase+kc+kk)*NNV + n0 + col];
        }
        __syncthreads();
#pragma unroll
        for (int k = 0; k < 16; k++) {
            float4 a4 = *(const float4*)&As[k][ty*4];
            float4 b4 = *(const float4*)&Bs[k][tx*4];
            float a[4] = {a4.x,a4.y,a4.z,a4.w};
            float b[4] = {b4.x,b4.y,b4.z,b4.w};
#pragma unroll
            for (int i = 0; i < 4; i++)
#pragma unroll
                for (int j = 0; j < 4; j++) acc[i][j] += a[i]*b[j];
        }
        __syncthreads();
    }
    float* out = &g_simpart[(size_t)blockIdx.z*NNV*NNV];
#pragma unroll
    for (int i = 0; i < 4; i++)
#pragma unroll
        for (int j = 0; j < 4; j++)
            out[(size_t)(m0+ty*4+i)*NNV + n0+tx*4+j] = acc[i][j];
}

__global__ void k_simred() {
    int i = blockIdx.x*256 + threadIdx.x;
    if (i >= NNV*NNV) return;
    float s = 0.f;
#pragma unroll
    for (int z = 0; z < 8; z++) s += g_simpart[(size_t)z*NNV*NNV + i];
    g_sim[i] = s;
}

// ------------------------- 3. top-45 per row --------------------------------
__global__ void k_topk() {
    __shared__ float vals[NNV];
    __shared__ float rv[128];
    __shared__ int   ri[128];
    int n = blockIdx.x, tid = threadIdx.x;
    for (int j = tid; j < NNV; j += 128)
        vals[j] = (j == n) ? -3.0e38f : g_sim[(size_t)n*NNV + j];
    __syncthreads();
    for (int it = 0; it < TKV; it++) {
        float best = -3.3e38f; int bi = NNV;
        for (int j = tid; j < NNV; j += 128) {
            float v = vals[j];
            if (v > best) { best = v; bi = j; }
        }
        rv[tid] = best; ri[tid] = bi;
        __syncthreads();
        for (int s2 = 64; s2; s2 >>= 1) {
            if (tid < s2) {
                float v2 = rv[tid+s2]; int i2 = ri[tid+s2];
                if (v2 > rv[tid] || (v2 == rv[tid] && i2 < ri[tid])) { rv[tid]=v2; ri[tid]=i2; }
            }
            __syncthreads();
        }
        if (tid == 0) { g_topk[n*TKV + it] = ri[0]; vals[ri[0]] = -3.0e38f; }
        __syncthreads();
    }
}

// ------------------------- 4. per-(b,n) partial sums over L -----------------
__global__ void k_partsums(const float* __restrict__ x) {
    int b = blockIdx.x >> 4, ch = blockIdx.x & 15;
    for (int n = threadIdx.x; n < NNV; n += 256) {
        float s = 0.f, q = 0.f;
        const float* p = x + ((size_t)b*LL + ch*128)*NNV + n;
        for (int l = 0; l < 128; l++) { float v = p[(size_t)l*NNV]; s += v; q += v*v; }
        g_ps[(size_t)blockIdx.x*NNV + n] = s;
        g_pq[(size_t)blockIdx.x*NNV + n] = q;
    }
}

// ------------------------- 5. router head -----------------------------------
__global__ void k_router(const float* __restrict__ var_embed,
                         const float* __restrict__ temp_w, const float* __restrict__ temp_b,
                         const float* __restrict__ q_w, const float* __restrict__ q_b,
                         const float* __restrict__ k_w, const float* __restrict__ k_b,
                         const float* __restrict__ imp_w, const float* __restrict__ imp_b) {
    int idx = blockIdx.x*256 + threadIdx.x;
    if (idx >= BB*NNV) return;
    int n = idx & (NNV-1);
    int b = idx >> 9;
    float s = 0.f, q = 0.f;
#pragma unroll
    for (int ch = 0; ch < 16; ch++) {
        s += g_ps[(size_t)(b*16+ch)*NNV + n];
        q += g_pq[(size_t)(b*16+ch)*NNV + n];
    }
    float mean = s * (1.0f/LL);
    float var  = (q - s*mean) * (1.0f/(LL-1));
    float stdv = sqrtf(var + 1e-5f);
    g_summary[idx] = mean;

    float vf[32];
#pragma unroll
    for (int h = 0; h < 16; h++) vf[h] = var_embed[n*16 + h];
#pragma unroll
    for (int h = 0; h < 16; h++) vf[16+h] = mean*temp_w[h] + stdv*temp_w[16+h] + temp_b[h];

    float ip = imp_b[0];
#pragma unroll
    for (int j = 0; j < 32; j++) ip += vf[j]*imp_w[j];
    g_imp[idx] = 1.f/(1.f + expf(-ip));

#pragma unroll
    for (int h = 0; h < 16; h++) {
        float qa = q_b[h], ka = k_b[h];
#pragma unroll
        for (int j = 0; j < 32; j++) { qa += vf[j]*q_w[j*16+h]; ka += vf[j]*k_w[j*16+h]; }
        g_Q[(size_t)idx*16 + h] = qa;
        g_K[(size_t)idx*16 + h] = ka;
    }
}

// ------------------------- 6. sparse attention softmax ----------------------
__global__ void k_attn() {
    int w = threadIdx.x >> 5, lane = threadIdx.x & 31;
    int id = blockIdx.x*8 + w;          // b*512+n
    int n = id & 511;
    int b = id >> 9;
    float qv[16];
#pragma unroll
    for (int h = 0; h < 16; h++) qv[h] = g_Q[(size_t)id*16 + h];
    int m1 = g_topk[n*TKV + lane];
    float s1 = 0.f;
#pragma unroll
    for (int h = 0; h < 16; h++) s1 += qv[h]*g_K[((size_t)b*512+m1)*16 + h];
    s1 *= 0.25f;
    float s2 = -3.0e38f;
    if (lane < TKV-32) {
        int m2 = g_topk[n*TKV + 32 + lane];
        float t = 0.f;
#pragma unroll
        for (int h = 0; h < 16; h++) t += qv[h]*g_K[((size_t)b*512+m2)*16 + h];
        s2 = t * 0.25f;
    }
    float mx = fmaxf(s1, s2);
#pragma unroll
    for (int o = 16; o; o >>= 1) mx = fmaxf(mx, __shfl_xor_sync(0xffffffffu, mx, o));
    float e1 = expf(s1 - mx);
    float e2 = (lane < TKV-32) ? expf(s2 - mx) : 0.f;
    float sm = e1 + e2;
#pragma unroll
    for (int o = 16; o; o >>= 1) sm += __shfl_xor_sync(0xffffffffu, sm, o);
    float inv = 1.f/sm;
    g_attn[(size_t)id*TKV + lane] = e1*inv;
    if (lane < TKV-32) g_attn[(size_t)id*TKV + 32 + lane] = e2*inv;
}

// ------------------------- 7. ring gather + mix ------------------------------
__global__ void k_ring(const float* __restrict__ x) {
    __shared__ float xs[512*17];
    int b = blockIdx.z, l0 = blockIdx.y*16, nc = blockIdx.x;
    const float* xp = x + ((size_t)b*LL + l0)*NNV;
    for (int i = threadIdx.x; i < 16*512; i += 256) {
        int l = i >> 9, n = i & 511;
        xs[n*17 + l] = xp[(size_t)l*NNV + n];
    }
    __syncthreads();
    int n = nc*256 + threadIdx.x;
    float acc[16];
#pragma unroll
    for (int l = 0; l < 16; l++) acc[l] = 0.f;
    size_t abase = ((size_t)b*512 + n)*TKV;
    int ibase = n*TKV;
    for (int k = 0; k < TKV; k++) {
        float a = g_attn[abase + k];
        int m = g_topk[ibase + k];
        const float* xm = &xs[m*17];
#pragma unroll
        for (int l = 0; l < 16; l++) acc[l] += a*xm[l];
    }
    float imp = g_imp[b*512 + n];
    float omi = 1.f - imp;
    const float* xn = &xs[n*17];
#pragma unroll
    for (int l = 0; l < 16; l++)
        g_ring[((size_t)b*LL + l0 + l)*NNV + n] = imp*acc[l] + omi*xn[l];
}

// ------------------------- 8. cluster weights + folded constants ------------
__global__ void k_cw(const float* __restrict__ cluster_score) {
    int n = blockIdx.x*256 + threadIdx.x;
    if (n >= NNV) return;
    float v[16], mx = -3e38f;
#pragma unroll
    for (int c = 0; c < 16; c++) { v[c] = cluster_score[n*16+c]; mx = fmaxf(mx, v[c]); }
    float s = 0.f;
#pragma unroll
    for (int c = 0; c < 16; c++) { v[c] = expf(v[c]-mx); s += v[c]; }
    float inv = 1.f/s;
#pragma unroll
    for (int c = 0; c < 16; c++) {
        float e = v[c]*inv;
        g_cw[n*16+c] = e;
        g_cwT[c*512+n] = e;
    }
}

__global__ void k_prep(const float* __restrict__ varproj_w, const float* __restrict__ varproj_b,
                       const float* __restrict__ cp1_w, const float* __restrict__ cp1_b,
                       const float* __restrict__ cp2_w, const float* __restrict__ cp2_b) {
    int tid = threadIdx.x;
    for (int id = tid; id < 1024; id += 256) {
        int c = id >> 6, e = id & 63;
        float s = 0.f;
        for (int d = 0; d < 64; d++) s += varproj_w[c*64+d]*cp1_w[d*64+e];
        g_M1[id] = s;
    }
    if (tid < 64) {
        int e = tid;
        float bbv = cp1_b[e];
        for (int d = 0; d < 64; d++) bbv += varproj_b[d]*cp1_w[d*64+e];
        g_bb[e] = bbv;
        float w2 = 0.f;
        for (int d = 0; d < 64; d++) w2 += cp2_w[e*64+d];
        g_w2[e] = w2;
    }
    if (tid == 0) {
        float s = 0.f;
        for (int d = 0; d < 64; d++) s += cp2_b[d];
        g_b2s = s;
    }
}

// ------------------------- 9. center tokens + projection --------------------
__global__ void k_ct(const float* __restrict__ cg_w, const float* __restrict__ cg_b) {
    int b = blockIdx.x;
    int j = blockIdx.y*256 + threadIdx.x;
    float s = cg_b[j];
    for (int n = 0; n < NNV; n++) s += g_summary[b*512+n]*cg_w[(size_t)n*1024 + j];
    g_ct[b*1024 + j] = s;
}

__global__ void k_ctp(const float* __restrict__ cp1_w) {
    int id = blockIdx.x*256 + threadIdx.x;
    if (id >= BB*16*64) return;
    int b = id >> 10, c = (id >> 6) & 15, e = id & 63;
    float s = 0.f;
    for (int d = 0; d < 64; d++) s += g_ct[b*1024 + c*64 + d]*cp1_w[d*64+e];
    g_ctp[id] = s;
}

// ------------------------- 10. xcs = x @ cw ---------------------------------
__global__ void k_xcs(const float* __restrict__ x) {
    __shared__ float xs[16*512];
    int row0 = blockIdx.x*16;
    const float* xp = x + (size_t)row0*NNV;
    for (int i = threadIdx.x; i < 16*512; i += 256) xs[i] = xp[i];
    __syncthreads();
    int l = threadIdx.x >> 4, c = threadIdx.x & 15;
    float s = 0.f;
    for (int n = 0; n < NNV; n++) s += xs[l*512+n]*__ldg(&g_cw[n*16+c]);
    g_xcs[(size_t)(row0+l)*16 + c] = s;
}

// ------------------------- 11. Sc (gelu-folded) + c2v -----------------------
__global__ void k_scc2v() {
    __shared__ float sxc[16], sx[64], red[128], sSc[16];
    size_t bl = blockIdx.x;
    int b = (int)(bl >> 11);
    int tid = threadIdx.x;
    if (tid < 16) sxc[tid] = g_xcs[bl*16 + tid];
    __syncthreads();
    if (tid < 64) {
        float s = g_bb[tid];
#pragma unroll
        for (int c = 0; c < 16; c++) s += sxc[c]*g_M1[c*64 + tid];
        sx[tid] = s;
    }
    __syncthreads();
    int c = tid >> 3, gi = tid & 7;
    float p = 0.f;
    const float* ctp = &g_ctp[(size_t)b*1024 + c*64];
#pragma unroll
    for (int ee = 0; ee < 8; ee++) {
        int e = gi*8 + ee;
        float t = sx[e] + ctp[e];
        p += (0.5f*t*(1.f + erff(t*0.70710678118654752f)))*g_w2[e];
    }
    red[tid] = p;
    __syncthreads();
    if (tid < 16) {
        float s = g_b2s;
#pragma unroll
        for (int gg = 0; gg < 8; gg++) s += red[tid*8 + gg];
        sSc[tid] = s;
    }
    __syncthreads();
    float sc[16];
#pragma unroll
    for (int cc = 0; cc < 16; cc++) sc[cc] = sSc[cc];
    float* op = &g_c2v[bl*NNV];
    for (int n = tid; n < NNV; n += 128) {
        float a = 0.f;
#pragma unroll
        for (int cc = 0; cc < 16; cc++) a += sc[cc]*__ldg(&g_cwT[cc*512 + n]);
        op[n] = a;
    }
}

// ------------------------- 12. big GEMMs (gate / fuse) ----------------------
template<int EP>
__global__ void k_gemm(const float* __restrict__ A1, const float* __restrict__ A2,
                       const float* __restrict__ Bw, const float* __restrict__ bias,
                       const float* __restrict__ aux, float* __restrict__ out, int Ktot) {
    __shared__ float As[16][132];
    __shared__ float Bs[16][128];
    int tid = threadIdx.x;
    int row0 = blockIdx.y*128, n0 = blockIdx.x*128;
    int tx = tid & 15, ty = tid >> 4;
    float acc[8][8];
#pragma unroll
    for (int i = 0; i < 8; i++)
#pragma unroll
        for (int j = 0; j < 8; j++) acc[i][j] = 0.f;

    for (int k0 = 0; k0 < Ktot; k0 += 16) {
        const float* Ap = (k0 < 512) ? A1 : A2;
        int kk = k0 & 511;
#pragma unroll
        for (int j = 0; j < 2; j++) {
            int f = tid + j*256;
            int m = f >> 2, q = f & 3;
            float4 v = *(const float4*)(Ap + (size_t)(row0+m)*512 + kk + q*4);
            As[q*4+0][m] = v.x; As[q*4+1][m] = v.y; As[q*4+2][m] = v.z; As[q*4+3][m] = v.w;
        }
#pragma unroll
        for (int j = 0; j < 2; j++) {
            int f = tid + j*256;
            int k = f >> 5, nq = f & 31;
            *(float4*)&Bs[k][nq*4] = *(const float4*)(Bw + (size_t)(k0+k)*512 + n0 + nq*4);
        }
        __syncthreads();
#pragma unroll
        for (int k = 0; k < 16; k++) {
            float a[8], bv[8];
            *(float4*)a     = *(float4*)&As[k][ty*8];
            *(float4*)(a+4) = *(float4*)&As[k][ty*8+4];
            *(float4*)bv     = *(float4*)&Bs[k][tx*8];
            *(float4*)(bv+4) = *(float4*)&Bs[k][tx*8+4];
#pragma unroll
            for (int i = 0; i < 8; i++)
#pragma unroll
                for (int j = 0; j < 8; j++) acc[i][j] += a[i]*bv[j];
        }
        __syncthreads();
    }
#pragma unroll
    for (int i = 0; i < 8; i++) {
        size_t row = row0 + ty*8 + i;
#pragma unroll
        for (int jq = 0; jq < 2; jq++) {
            int col0 = n0 + tx*8 + jq*4;
            float4 o4;
            float* ov = (float*)&o4;
#pragma unroll
            for (int j = 0; j < 4; j++) {
                int col = col0 + j;
                float s = acc[i][jq*4+j] + bias[col];
                if (EP == 0) {
                    float g = 1.f/(1.f + expf(-s));
                    float r = A1[row*512 + col];
                    float cv = A2[row*512 + col];
                    ov[j] = g*r + (1.f-g)*cv;
                } else {
                    ov[j] = s + aux[row*512 + col];
                }
            }
            *(float4*)(out + row*512 + col0) = o4;
        }
    }
}

// ------------------------- 13. layernorm -------------------------------------
__global__ void k_ln(const float* __restrict__ lng, const float* __restrict__ lnb,
                     float* __restrict__ out) {
    __shared__ float ss[4], sq[4];
    int row = blockIdx.x, tid = threadIdx.x;
    float4 h4 = ((const float4*)(g_h + (size_t)row*NNV))[tid];
    float s = h4.x + h4.y + h4.z + h4.w;
    float q = h4.x*h4.x + h4.y*h4.y + h4.z*h4.z + h4.w*h4.w;
#pragma unroll
    for (int o = 16; o; o >>= 1) {
        s += __shfl_xor_sync(0xffffffffu, s, o);
        q += __shfl_xor_sync(0xffffffffu, q, o);
    }
    if ((tid & 31) == 0) { ss[tid>>5] = s; sq[tid>>5] = q; }
    __syncthreads();
    s = ss[0] + ss[1] + ss[2] + ss[3];
    q = sq[0] + sq[1] + sq[2] + sq[3];
    float mu = s*(1.f/NNV);
    float var = q*(1.f/NNV) - mu*mu;
    float inv = rsqrtf(var + 1e-5f);
    float4 g4 = ((const float4*)lng)[tid];
    float4 b4 = ((const float4*)lnb)[tid];
    float4 o4;
    o4.x = (h4.x - mu)*inv*g4.x + b4.x;
    o4.y = (h4.y - mu)*inv*g4.y + b4.y;
    o4.z = (h4.z - mu)*inv*g4.z + b4.z;
    o4.w = (h4.w - mu)*inv*g4.w + b4.w;
    ((float4*)(out + (size_t)row*NNV))[tid] = o4;
}

// ------------------------- launch --------------------------------------------
extern "C" void kernel_launch(void* const* d_in, const int* in_sizes, int n_in,
                              void* d_out, int out_size) {
    const float* x          = (const float*)d_in[0];
    const float* var_embed  = (const float*)d_in[1];
    const float* temp_w     = (const float*)d_in[2];
    const float* temp_b     = (const float*)d_in[3];
    const float* q_w        = (const float*)d_in[4];
    const float* q_b        = (const float*)d_in[5];
    const float* k_w        = (const float*)d_in[6];
    const float* k_b        = (const float*)d_in[7];
    const float* imp_w      = (const float*)d_in[8];
    const float* imp_b      = (const float*)d_in[9];
    const float* cluster_sc = (const float*)d_in[10];
    const float* varproj_w  = (const float*)d_in[11];
    const float* varproj_b  = (const float*)d_in[12];
    const float* cp1_w      = (const float*)d_in[13];
    const float* cp1_b      = (const float*)d_in[14];
    const float* cp2_w      = (const float*)d_in[15];
    const float* cp2_b      = (const float*)d_in[16];
    const float* cg_w       = (const float*)d_in[17];
    const float* cg_b       = (const float*)d_in[18];
    const float* gate_w     = (const float*)d_in[19];
    const float* gate_b     = (const float*)d_in[20];
    const float* fus_w      = (const float*)d_in[21];
    const float* fus_b      = (const float*)d_in[22];
    const float* ln_g       = (const float*)d_in[23];
    const float* ln_b       = (const float*)d_in[24];
    float* out = (float*)d_out;

    float *p_ring, *p_c2v, *p_fusedv, *p_h;
    cudaGetSymbolAddress((void**)&p_ring,   g_ring);
    cudaGetSymbolAddress((void**)&p_c2v,    g_c2v);
    cudaGetSymbolAddress((void**)&p_fusedv, g_fusedv);
    cudaGetSymbolAddress((void**)&p_h,      g_h);

    // mask path
    k_colstats<<<(LL*NNV+255)/256, 256>>>(x);
    k_sim<<<dim3(8,8,8), 256>>>();
    k_simred<<<NNV*NNV/256, 256>>>();
    k_topk<<<NNV, 128>>>();

    // router path
    k_partsums<<<BB*16, 256>>>(x);
    k_router<<<BB*NNV/256, 256>>>(var_embed, temp_w, temp_b, q_w, q_b, k_w, k_b, imp_w, imp_b);
    k_attn<<<BB*NNV/8, 256>>>();
    k_ring<<<dim3(2, LL/16, BB), 256>>>(x);

    // center path
    k_cw<<<2, 256>>>(cluster_sc);
    k_prep<<<1, 256>>>(varproj_w, varproj_b, cp1_w, cp1_b, cp2_w, cp2_b);
    k_ct<<<dim3(BB, 4), 256>>>(cg_w, cg_b);
    k_ctp<<<BB*16*64/256, 256>>>(cp1_w);
    k_xcs<<<BLV/16, 256>>>(x);
    k_scc2v<<<BLV, 128>>>();

    // fusion GEMMs + layernorm
    k_gemm<0><<<dim3(4, BLV/128), 256>>>(p_ring, p_c2v, gate_w, gate_b, p_ring, p_fusedv, 1024);
    k_gemm<1><<<dim3(4, BLV/128), 256>>>(p_fusedv, p_fusedv, fus_w, fus_b, x, p_h, 512);
    k_ln<<<BLV, 128>>>(ln_g, ln_b, out);

    (void)in_sizes; (void)n_in; (void)out_size;
}

// round 4
// speedup vs baseline: 1.5407x; 1.5407x over previous
#include <cuda_runtime.h>
#include <cuda_bf16.h>
#include <math.h>
#include <stddef.h>
#include <stdint.h>

#define BB 8
#define LL 2048
#define NNV 512
#define HHV 16
#define CCV 16
#define DDV 64
#define TKV 45
#define BLV (BB*LL)
#define KEXT 576   // 512 + 16 (rank-16 fold) + 48 zero pad

__device__ __forceinline__ void bfsplit(float v, __nv_bfloat16& h, __nv_bfloat16& l) {
    h = __float2bfloat16(v);
    l = __float2bfloat16(v - __bfloat162float(h));
}

__device__ __forceinline__ void mma16816(float& c0, float& c1, float& c2, float& c3,
                                         uint32_t a0, uint32_t a1, uint32_t a2, uint32_t a3,
                                         uint32_t b0, uint32_t b1) {
    asm volatile(
        "mma.sync.aligned.m16n8k16.row.col.f32.bf16.bf16.f32 "
        "{%0,%1,%2,%3}, {%4,%5,%6,%7}, {%8,%9}, {%0,%1,%2,%3};"
        : "+f"(c0), "+f"(c1), "+f"(c2), "+f"(c3)
        : "r"(a0), "r"(a1), "r"(a2), "r"(a3), "r"(b0), "r"(b1));
}

// ===================== scratch (device globals) =====================
__device__ float g_normed[LL*NNV];
__device__ float g_simpart[8*NNV*NNV];
__device__ float g_sim[NNV*NNV];
__device__ int   g_topk[NNV*TKV];
__device__ float g_attn[BB*NNV*TKV];
__device__ float g_Q[BB*NNV*HHV];
__device__ float g_K[BB*NNV*HHV];
__device__ float g_imp[BB*NNV];
__device__ float g_summary[BB*NNV];
__device__ float g_ps[BB*16*NNV];
__device__ float g_pq[BB*16*NNV];
__device__ float g_cw[NNV*CCV];
__device__ float g_cwT[CCV*NNV];
__device__ float g_M1[CCV*DDV];
__device__ float g_bb[DDV];
__device__ float g_w2[DDV];
__device__ float g_b2s;
__device__ float g_ct[BB*CCV*DDV];
__device__ float g_ctp[BB*CCV*DDV];
__device__ float g_xcs[(size_t)BLV*CCV];
__device__ float g_ring[(size_t)BLV*NNV];
__device__ float g_c2v[(size_t)BLV*NNV];
__device__ float g_h[(size_t)BLV*NNV];
__device__ __nv_bfloat16 g_A1h[(size_t)BLV*KEXT];
__device__ __nv_bfloat16 g_A1l[(size_t)BLV*KEXT];
__device__ __nv_bfloat16 g_A2h[(size_t)BLV*KEXT];
__device__ __nv_bfloat16 g_A2l[(size_t)BLV*KEXT];
__device__ __nv_bfloat16 g_B1h[NNV*KEXT];
__device__ __nv_bfloat16 g_B1l[NNV*KEXT];
__device__ __nv_bfloat16 g_B2h[NNV*KEXT];
__device__ __nv_bfloat16 g_B2l[NNV*KEXT];

// ===================== 1. column stats over batch =====================
__global__ void k_colstats(const float* __restrict__ x) {
    int i = blockIdx.x * 256 + threadIdx.x;
    if (i >= LL*NNV) return;
    float v[BB];
#pragma unroll
    for (int b = 0; b < BB; b++) v[b] = x[(size_t)b*LL*NNV + i];
    float s = 0.f;
#pragma unroll
    for (int b = 0; b < BB; b++) s += v[b];
    float mean = s * (1.0f/BB);
    float q = 0.f;
#pragma unroll
    for (int b = 0; b < BB; b++) { float d = v[b]-mean; q += d*d; }
    float stdv = sqrtf(q * (1.0f/(BB-1))) + 1e-5f;
    g_normed[i] = mean / stdv;
}

// ===================== 2. sim = normed^T normed (split-K) =====================
__global__ void k_sim() {
    __shared__ float As[16][64];
    __shared__ float Bs[16][64];
    int tid = threadIdx.x;
    int tx = tid & 15, ty = tid >> 4;
    int m0 = blockIdx.y*64, n0 = blockIdx.x*64, lbase = blockIdx.z*256;
    float acc[4][4];
#pragma unroll
    for (int i = 0; i < 4; i++)
#pragma unroll
        for (int j = 0; j < 4; j++) acc[i][j] = 0.f;
    for (int kc = 0; kc < 256; kc += 16) {
#pragma unroll
        for (int t = 0; t < 4; t++) {
            int fid = tid + t*256;
            int kk = fid >> 6, col = fid & 63;
            As[kk][col] = g_normed[(size_t)(lbase+kc+kk)*NNV + m0 + col];
            Bs[kk][col] = g_normed[(size_t)(lbase+kc+kk)*NNV + n0 + col];
        }
        __syncthreads();
#pragma unroll
        for (int k = 0; k < 16; k++) {
            float4 a4 = *(const float4*)&As[k][ty*4];
            float4 b4 = *(const float4*)&Bs[k][tx*4];
            float a[4] = {a4.x,a4.y,a4.z,a4.w};
            float b[4] = {b4.x,b4.y,b4.z,b4.w};
#pragma unroll
            for (int i = 0; i < 4; i++)
#pragma unroll
                for (int j = 0; j < 4; j++) acc[i][j] += a[i]*b[j];
        }
        __syncthreads();
    }
    float* out = &g_simpart[(size_t)blockIdx.z*NNV*NNV];
#pragma unroll
    for (int i = 0; i < 4; i++)
#pragma unroll
        for (int j = 0; j < 4; j++)
            out[(size_t)(m0+ty*4+i)*NNV + n0+tx*4+j] = acc[i][j];
}

__global__ void k_simred() {
    int i = blockIdx.x*256 + threadIdx.x;
    if (i >= NNV*NNV) return;
    float s = 0.f;
#pragma unroll
    for (int z = 0; z < 8; z++) s += g_simpart[(size_t)z*NNV*NNV + i];
    g_sim[i] = s;
}

// ===================== 3. top-45 per row (warp per row) =====================
__global__ void k_topk() {
    int warp = threadIdx.x >> 5, lane = threadIdx.x & 31;
    int n = blockIdx.x*4 + warp;
    float v[16];
#pragma unroll
    for (int j = 0; j < 16; j++) {
        int col = j*32 + lane;
        v[j] = (col == n) ? -3.0e38f : g_sim[(size_t)n*NNV + col];
    }
    float lm = -3.0e38f; int li = 0;
#pragma unroll
    for (int j = 0; j < 16; j++) if (v[j] > lm) { lm = v[j]; li = j; }
    for (int it = 0; it < TKV; it++) {
        float m = lm; int src = lane;
#pragma unroll
        for (int o = 16; o; o >>= 1) {
            float om = __shfl_xor_sync(0xffffffffu, m, o);
            int os = __shfl_xor_sync(0xffffffffu, src, o);
            if (om > m || (om == m && os < src)) { m = om; src = os; }
        }
        int wli = __shfl_sync(0xffffffffu, li, src);
        if (lane == 0) g_topk[n*TKV + it] = wli*32 + src;
        if (lane == src) {
#pragma unroll
            for (int j = 0; j < 16; j++) if (j == li) v[j] = -3.0e38f;
            lm = -3.0e38f; li = 0;
#pragma unroll
            for (int j = 0; j < 16; j++) if (v[j] > lm) { lm = v[j]; li = j; }
        }
    }
}

// ===================== 4. per-(b,n) partial sums over L =====================
__global__ void k_partsums(const float* __restrict__ x) {
    int b = blockIdx.x >> 4, ch = blockIdx.x & 15;
    for (int n = threadIdx.x; n < NNV; n += 256) {
        float s = 0.f, q = 0.f;
        const float* p = x + ((size_t)b*LL + ch*128)*NNV + n;
        for (int l = 0; l < 128; l++) { float v = p[(size_t)l*NNV]; s += v; q += v*v; }
        g_ps[(size_t)blockIdx.x*NNV + n] = s;
        g_pq[(size_t)blockIdx.x*NNV + n] = q;
    }
}

// ===================== 5. router head =====================
__global__ void k_router(const float* __restrict__ var_embed,
                         const float* __restrict__ temp_w, const float* __restrict__ temp_b,
                         const float* __restrict__ q_w, const float* __restrict__ q_b,
                         const float* __restrict__ k_w, const float* __restrict__ k_b,
                         const float* __restrict__ imp_w, const float* __restrict__ imp_b) {
    int idx = blockIdx.x*256 + threadIdx.x;
    if (idx >= BB*NNV) return;
    int n = idx & (NNV-1);
    int b = idx >> 9;
    float s = 0.f, q = 0.f;
#pragma unroll
    for (int ch = 0; ch < 16; ch++) {
        s += g_ps[(size_t)(b*16+ch)*NNV + n];
        q += g_pq[(size_t)(b*16+ch)*NNV + n];
    }
    float mean = s * (1.0f/LL);
    float var  = (q - s*mean) * (1.0f/(LL-1));
    float stdv = sqrtf(var + 1e-5f);
    g_summary[idx] = mean;

    float vf[32];
#pragma unroll
    for (int h = 0; h < 16; h++) vf[h] = var_embed[n*16 + h];
#pragma unroll
    for (int h = 0; h < 16; h++) vf[16+h] = mean*temp_w[h] + stdv*temp_w[16+h] + temp_b[h];

    float ip = imp_b[0];
#pragma unroll
    for (int j = 0; j < 32; j++) ip += vf[j]*imp_w[j];
    g_imp[idx] = 1.f/(1.f + expf(-ip));

#pragma unroll
    for (int h = 0; h < 16; h++) {
        float qa = q_b[h], ka = k_b[h];
#pragma unroll
        for (int j = 0; j < 32; j++) { qa += vf[j]*q_w[j*16+h]; ka += vf[j]*k_w[j*16+h]; }
        g_Q[(size_t)idx*16 + h] = qa;
        g_K[(size_t)idx*16 + h] = ka;
    }
}

// ===================== 6. sparse attention softmax =====================
__global__ void k_attn() {
    int w = threadIdx.x >> 5, lane = threadIdx.x & 31;
    int id = blockIdx.x*8 + w;
    int n = id & 511;
    int b = id >> 9;
    float qv[16];
#pragma unroll
    for (int h = 0; h < 16; h++) qv[h] = g_Q[(size_t)id*16 + h];
    int m1 = g_topk[n*TKV + lane];
    float s1 = 0.f;
#pragma unroll
    for (int h = 0; h < 16; h++) s1 += qv[h]*g_K[((size_t)b*512+m1)*16 + h];
    s1 *= 0.25f;
    float s2 = -3.0e38f;
    if (lane < TKV-32) {
        int m2 = g_topk[n*TKV + 32 + lane];
        float t = 0.f;
#pragma unroll
        for (int h = 0; h < 16; h++) t += qv[h]*g_K[((size_t)b*512+m2)*16 + h];
        s2 = t * 0.25f;
    }
    float mx = fmaxf(s1, s2);
#pragma unroll
    for (int o = 16; o; o >>= 1) mx = fmaxf(mx, __shfl_xor_sync(0xffffffffu, mx, o));
    float e1 = expf(s1 - mx);
    float e2 = (lane < TKV-32) ? expf(s2 - mx) : 0.f;
    float sm = e1 + e2;
#pragma unroll
    for (int o = 16; o; o >>= 1) sm += __shfl_xor_sync(0xffffffffu, sm, o);
    float inv = 1.f/sm;
    g_attn[(size_t)id*TKV + lane] = e1*inv;
    if (lane < TKV-32) g_attn[(size_t)id*TKV + 32 + lane] = e2*inv;
}

// ===================== 7. ring gather + mix (fp32 + bf16 hi/lo) ======
__global__ void k_ring(const float* __restrict__ x) {
    __shared__ float xs[512*17];
    int b = blockIdx.z, l0 = blockIdx.y*16, nc = blockIdx.x;
    const float* xp = x + ((size_t)b*LL + l0)*NNV;
    for (int i = threadIdx.x; i < 16*512; i += 256) {
        int l = i >> 9, n = i & 511;
        xs[n*17 + l] = xp[(size_t)l*NNV + n];
    }
    __syncthreads();
    int n = nc*256 + threadIdx.x;
    float acc[16];
#pragma unroll
    for (int l = 0; l < 16; l++) acc[l] = 0.f;
    size_t abase = ((size_t)b*512 + n)*TKV;
    int ibase = n*TKV;
    for (int k = 0; k < TKV; k++) {
        float a = g_attn[abase + k];
        int m = g_topk[ibase + k];
        const float* xm = &xs[m*17];
#pragma unroll
        for (int l = 0; l < 16; l++) acc[l] += a*xm[l];
    }
    float imp = g_imp[b*512 + n];
    float omi = 1.f - imp;
    const float* xn = &xs[n*17];
#pragma unroll
    for (int l = 0; l < 16; l++) {
        size_t row = (size_t)b*LL + l0 + l;
        float v = imp*acc[l] + omi*xn[l];
        g_ring[row*NNV + n] = v;
        __nv_bfloat16 h, lo;
        bfsplit(v, h, lo);
        g_A1h[row*KEXT + n] = h;
        g_A1l[row*KEXT + n] = lo;
    }
}

// ===================== 8. cluster weights =====================
__global__ void k_cw(const float* __restrict__ cluster_score) {
    int n = blockIdx.x*256 + threadIdx.x;
    if (n >= NNV) return;
    float v[16], mx = -3e38f;
#pragma unroll
    for (int c = 0; c < 16; c++) { v[c] = cluster_score[n*16+c]; mx = fmaxf(mx, v[c]); }
    float s = 0.f;
#pragma unroll
    for (int c = 0; c < 16; c++) { v[c] = expf(v[c]-mx); s += v[c]; }
    float inv = 1.f/s;
#pragma unroll
    for (int c = 0; c < 16; c++) {
        float e = v[c]*inv;
        g_cw[n*16+c] = e;
        g_cwT[c*512+n] = e;
    }
}

__global__ void k_prep(const float* __restrict__ varproj_w, const float* __restrict__ varproj_b,
                       const float* __restrict__ cp1_w, const float* __restrict__ cp1_b,
                       const float* __restrict__ cp2_w, const float* __restrict__ cp2_b) {
    int tid = threadIdx.x;
    for (int id = tid; id < 1024; id += 256) {
        int c = id >> 6, e = id & 63;
        float s = 0.f;
        for (int d = 0; d < 64; d++) s += varproj_w[c*64+d]*cp1_w[d*64+e];
        g_M1[id] = s;
    }
    if (tid < 64) {
        int e = tid;
        float bbv = cp1_b[e];
        for (int d = 0; d < 64; d++) bbv += varproj_b[d]*cp1_w[d*64+e];
        g_bb[e] = bbv;
        float w2 = 0.f;
        for (int d = 0; d < 64; d++) w2 += cp2_w[e*64+d];
        g_w2[e] = w2;
    }
    if (tid == 0) {
        float s = 0.f;
        for (int d = 0; d < 64; d++) s += cp2_b[d];
        g_b2s = s;
    }
}

// ===== 8b. weight transpose + bf16 split + rank-16 fold (G2 = cwT @ Wr) =====
__global__ void k_prepw(const float* __restrict__ Wd, const float* __restrict__ Wr,
                        __nv_bfloat16* __restrict__ oh, __nv_bfloat16* __restrict__ ol) {
    __shared__ float colv[512];
    int n = blockIdx.x;
    int tid = threadIdx.x;   // 128 threads
    for (int k = tid; k < 512; k += 128) {
        float w = Wd[(size_t)k*512 + n];
        __nv_bfloat16 h, l;
        bfsplit(w, h, l);
        oh[(size_t)n*KEXT + k] = h;
        ol[(size_t)n*KEXT + k] = l;
    }
    for (int m = tid; m < 512; m += 128) colv[m] = Wr[(size_t)m*512 + n];
    __syncthreads();
    if (tid < 16) {
        float s = 0.f;
        for (int m = 0; m < 512; m++) s += g_cwT[tid*512 + m]*colv[m];
        __nv_bfloat16 h, l;
        bfsplit(s, h, l);
        oh[(size_t)n*KEXT + 512 + tid] = h;
        ol[(size_t)n*KEXT + 512 + tid] = l;
    } else if (tid < 64) {
        __nv_bfloat16 z = __float2bfloat16(0.f);
        oh[(size_t)n*KEXT + 512 + tid] = z;
        ol[(size_t)n*KEXT + 512 + tid] = z;
    }
}

// ===================== 9. center tokens + projection =====================
__global__ void k_ct(const float* __restrict__ cg_w, const float* __restrict__ cg_b) {
    int b = blockIdx.x;
    int j = blockIdx.y*256 + threadIdx.x;
    float s = cg_b[j];
    for (int n = 0; n < NNV; n++) s += g_summary[b*512+n]*cg_w[(size_t)n*1024 + j];
    g_ct[b*1024 + j] = s;
}

__global__ void k_ctp(const float* __restrict__ cp1_w) {
    int id = blockIdx.x*256 + threadIdx.x;
    if (id >= BB*16*64) return;
    int b = id >> 10;
    int cd = id & 1023;
    int c = cd >> 6, e = cd & 63;
    float s = 0.f;
    for (int d = 0; d < 64; d++) s += g_ct[b*1024 + c*64 + d]*cp1_w[d*64+e];
    g_ctp[id] = s;
}

// ===================== 10. xcs = x @ cw =====================
__global__ void k_xcs(const float* __restrict__ x) {
    __shared__ float xs[16*512];
    int row0 = blockIdx.x*16;
    const float* xp = x + (size_t)row0*NNV;
    for (int i = threadIdx.x; i < 16*512; i += 256) xs[i] = xp[i];
    __syncthreads();
    int l = threadIdx.x >> 4, c = threadIdx.x & 15;
    float s = 0.f;
    for (int n = 0; n < NNV; n++) s += xs[l*512+n]*__ldg(&g_cw[n*16+c]);
    g_xcs[(size_t)(row0+l)*16 + c] = s;
}

// ========== 11. Sc (gelu-folded) + c2v + Sc K-extension columns ==========
__global__ void k_scc2v() {
    __shared__ float sxc[16], sx[64], red[128], sSc[16];
    size_t bl = blockIdx.x;
    int b = (int)(bl >> 11);
    int tid = threadIdx.x;
    if (tid < 16) sxc[tid] = g_xcs[bl*16 + tid];
    __syncthreads();
    if (tid < 64) {
        float s = g_bb[tid];
#pragma unroll
        for (int c = 0; c < 16; c++) s += sxc[c]*g_M1[c*64 + tid];
        sx[tid] = s;
    }
    __syncthreads();
    int c = tid >> 3, gi = tid & 7;
    float p = 0.f;
    const float* ctp = &g_ctp[(size_t)b*1024 + c*64];
#pragma unroll
    for (int ee = 0; ee < 8; ee++) {
        int e = gi*8 + ee;
        float t = sx[e] + ctp[e];
        p += (0.5f*t*(1.f + erff(t*0.70710678118654752f)))*g_w2[e];
    }
    red[tid] = p;
    __syncthreads();
    if (tid < 16) {
        float s = g_b2s;
#pragma unroll
        for (int gg = 0; gg < 8; gg++) s += red[tid*8 + gg];
        sSc[tid] = s;
    }
    __syncthreads();
    if (tid < 16) {
        float v = sSc[tid];
        __nv_bfloat16 h, l;
        bfsplit(v, h, l);
        size_t o = bl*KEXT + 512 + tid;
        g_A1h[o] = h; g_A1l[o] = l;
        g_A2h[o] = h; g_A2l[o] = l;
    } else if (tid < 64) {
        __nv_bfloat16 z = __float2bfloat16(0.f);
        size_t o = bl*KEXT + 512 + tid;
        g_A1h[o] = z; g_A1l[o] = z;
        g_A2h[o] = z; g_A2l[o] = z;
    }
    float sc[16];
#pragma unroll
    for (int cc = 0; cc < 16; cc++) sc[cc] = sSc[cc];
    float* op = &g_c2v[bl*NNV];
    for (int n = tid; n < NNV; n += 128) {
        float a = 0.f;
#pragma unroll
        for (int cc = 0; cc < 16; cc++) a += sc[cc]*__ldg(&g_cwT[cc*512 + n]);
        op[n] = a;
    }
}

// ===================== 12. mma.sync bf16 3-pass GEMMs =====================
// CTA tile 128M x 64N, 8 warps (4M x 2N), warp tile 32x32 = 2x4 mma tiles.
// smem (bf16 elems, row stride 72): AH[128][72] AL[128][72] BH[64][72] BL[64][72]
#define SROW 72
#define SM_AH 0
#define SM_AL (128*SROW)
#define SM_BH (256*SROW)
#define SM_BL (256*SROW + 64*SROW)
#define SM_TOT ((256*SROW + 128*SROW)*2)   // bytes: 384*72*2 = 55296

template<int EP>
__global__ void __launch_bounds__(256) k_mma(
    const __nv_bfloat16* __restrict__ Ah, const __nv_bfloat16* __restrict__ Al,
    const __nv_bfloat16* __restrict__ Bh, const __nv_bfloat16* __restrict__ Bl,
    const float* __restrict__ bias,
    const float* __restrict__ e0, const float* __restrict__ e1,
    __nv_bfloat16* __restrict__ o0, __nv_bfloat16* __restrict__ o1,
    float* __restrict__ outF)
{
    extern __shared__ __align__(16) __nv_bfloat16 sm[];
    int tid = threadIdx.x;
    int wid = tid >> 5, lane = tid & 31;
    int gr = lane >> 2, tc = lane & 3;
    int warpM = wid & 3, warpN = wid >> 2;
    int row0 = blockIdx.y * 128, col0 = blockIdx.x * 64;

    float acc[2][4][4];
#pragma unroll
    for (int mt = 0; mt < 2; mt++)
#pragma unroll
        for (int nt = 0; nt < 4; nt++)
#pragma unroll
            for (int i = 0; i < 4; i++) acc[mt][nt][i] = 0.f;

    for (int s = 0; s < 9; s++) {
        int k0 = s * 64;
        // ---- stage loads (vectorized uint4 = 8 bf16) ----
#pragma unroll
        for (int t = 0; t < 4; t++) {
            int i = tid + t*256;               // < 1024
            int r = i >> 3, c8 = (i & 7) * 8;
            const __nv_bfloat16* gh = Ah + (size_t)(row0+r)*KEXT + k0 + c8;
            const __nv_bfloat16* gl = Al + (size_t)(row0+r)*KEXT + k0 + c8;
            *(uint4*)(sm + SM_AH + r*SROW + c8) = *(const uint4*)gh;
            *(uint4*)(sm + SM_AL + r*SROW + c8) = *(const uint4*)gl;
        }
#pragma unroll
        for (int t = 0; t < 2; t++) {
            int i = tid + t*256;               // < 512
            int r = i >> 3, c8 = (i & 7) * 8;
            const __nv_bfloat16* gh = Bh + (size_t)(col0+r)*KEXT + k0 + c8;
            const __nv_bfloat16* gl = Bl + (size_t)(col0+r)*KEXT + k0 + c8;
            *(uint4*)(sm + SM_BH + r*SROW + c8) = *(const uint4*)gh;
            *(uint4*)(sm + SM_BL + r*SROW + c8) = *(const uint4*)gl;
        }
        __syncthreads();
        // ---- compute: 4 k16 steps ----
#pragma unroll
        for (int kk = 0; kk < 4; kk++) {
            int ko = kk*16 + tc*2;
            uint32_t aH[2][4], aL[2][4];
#pragma unroll
            for (int mt = 0; mt < 2; mt++) {
                int R = (warpM*32 + mt*16 + gr)*SROW + ko;
                aH[mt][0] = *(const uint32_t*)(sm + SM_AH + R);
                aH[mt][1] = *(const uint32_t*)(sm + SM_AH + R + 8*SROW);
                aH[mt][2] = *(const uint32_t*)(sm + SM_AH + R + 8);
                aH[mt][3] = *(const uint32_t*)(sm + SM_AH + R + 8*SROW + 8);
                aL[mt][0] = *(const uint32_t*)(sm + SM_AL + R);
                aL[mt][1] = *(const uint32_t*)(sm + SM_AL + R + 8*SROW);
                aL[mt][2] = *(const uint32_t*)(sm + SM_AL + R + 8);
                aL[mt][3] = *(const uint32_t*)(sm + SM_AL + R + 8*SROW + 8);
            }
            uint32_t bH[4][2], bL[4][2];
#pragma unroll
            for (int nt = 0; nt < 4; nt++) {
                int R = (warpN*32 + nt*8 + gr)*SROW + ko;
                bH[nt][0] = *(const uint32_t*)(sm + SM_BH + R);
                bH[nt][1] = *(const uint32_t*)(sm + SM_BH + R + 8);
                bL[nt][0] = *(const uint32_t*)(sm + SM_BL + R);
                bL[nt][1] = *(const uint32_t*)(sm + SM_BL + R + 8);
            }
#pragma unroll
            for (int mt = 0; mt < 2; mt++)
#pragma unroll
                for (int nt = 0; nt < 4; nt++) {
                    float* c = acc[mt][nt];
                    mma16816(c[0],c[1],c[2],c[3], aH[mt][0],aH[mt][1],aH[mt][2],aH[mt][3], bH[nt][0],bH[nt][1]);
                    mma16816(c[0],c[1],c[2],c[3], aH[mt][0],aH[mt][1],aH[mt][2],aH[mt][3], bL[nt][0],bL[nt][1]);
                    mma16816(c[0],c[1],c[2],c[3], aL[mt][0],aL[mt][1],aL[mt][2],aL[mt][3], bH[nt][0],bH[nt][1]);
                }
        }
        __syncthreads();
    }

    // ---- epilogue ----
#pragma unroll
    for (int mt = 0; mt < 2; mt++) {
#pragma unroll
        for (int half = 0; half < 2; half++) {
            int row = row0 + warpM*32 + mt*16 + gr + half*8;
#pragma unroll
            for (int nt = 0; nt < 4; nt++) {
                int col = col0 + warpN*32 + nt*8 + tc*2;
                float c0 = acc[mt][nt][half*2 + 0];
                float c1 = acc[mt][nt][half*2 + 1];
                float2 bs = *(const float2*)(bias + col);
                size_t ro = (size_t)row*512 + col;
                if (EP == 0) {
                    float2 rg = *(const float2*)(e0 + ro);
                    float2 cv = *(const float2*)(e1 + ro);
                    float g0 = 1.f/(1.f + __expf(-(c0 + bs.x)));
                    float g1 = 1.f/(1.f + __expf(-(c1 + bs.y)));
                    float t0 = g0*(rg.x - cv.x);
                    float t1 = g1*(rg.y - cv.y);
                    __nv_bfloat16 h0, l0, h1, l1;
                    bfsplit(t0, h0, l0); bfsplit(t1, h1, l1);
                    size_t ro6 = (size_t)row*KEXT + col;
                    __nv_bfloat162 hh; hh.x = h0; hh.y = h1;
                    __nv_bfloat162 llv; llv.x = l0; llv.y = l1;
                    *(__nv_bfloat162*)(o0 + ro6) = hh;
                    *(__nv_bfloat162*)(o1 + ro6) = llv;
                } else {
                    float2 xv = *(const float2*)(e0 + ro);
                    float2 hv;
                    hv.x = c0 + bs.x + xv.x;
                    hv.y = c1 + bs.y + xv.y;
                    *(float2*)(outF + ro) = hv;
                }
            }
        }
    }
}

// ===================== 13. layernorm =====================
__global__ void k_ln(const float* __restrict__ lng, const float* __restrict__ lnb,
                     float* __restrict__ out) {
    __shared__ float ss[4], sq[4];
    int row = blockIdx.x, tid = threadIdx.x;
    float4 h4 = ((const float4*)(g_h + (size_t)row*NNV))[tid];
    float s = h4.x + h4.y + h4.z + h4.w;
    float q = h4.x*h4.x + h4.y*h4.y + h4.z*h4.z + h4.w*h4.w;
#pragma unroll
    for (int o = 16; o; o >>= 1) {
        s += __shfl_xor_sync(0xffffffffu, s, o);
        q += __shfl_xor_sync(0xffffffffu, q, o);
    }
    if ((tid & 31) == 0) { ss[tid>>5] = s; sq[tid>>5] = q; }
    __syncthreads();
    s = ss[0] + ss[1] + ss[2] + ss[3];
    q = sq[0] + sq[1] + sq[2] + sq[3];
    float mu = s*(1.f/NNV);
    float var = q*(1.f/NNV) - mu*mu;
    float inv = rsqrtf(var + 1e-5f);
    float4 g4 = ((const float4*)lng)[tid];
    float4 b4 = ((const float4*)lnb)[tid];
    float4 o4;
    o4.x = (h4.x - mu)*inv*g4.x + b4.x;
    o4.y = (h4.y - mu)*inv*g4.y + b4.y;
    o4.z = (h4.z - mu)*inv*g4.z + b4.z;
    o4.w = (h4.w - mu)*inv*g4.w + b4.w;
    ((float4*)(out + (size_t)row*NNV))[tid] = o4;
}

// ===================== launch =====================
extern "C" void kernel_launch(void* const* d_in, const int* in_sizes, int n_in,
                              void* d_out, int out_size) {
    const float* x          = (const float*)d_in[0];
    const float* var_embed  = (const float*)d_in[1];
    const float* temp_w     = (const float*)d_in[2];
    const float* temp_b     = (const float*)d_in[3];
    const float* q_w        = (const float*)d_in[4];
    const float* q_b        = (const float*)d_in[5];
    const float* k_w        = (const float*)d_in[6];
    const float* k_b        = (const float*)d_in[7];
    const float* imp_w      = (const float*)d_in[8];
    const float* imp_b      = (const float*)d_in[9];
    const float* cluster_sc = (const float*)d_in[10];
    const float* varproj_w  = (const float*)d_in[11];
    const float* varproj_b  = (const float*)d_in[12];
    const float* cp1_w      = (const float*)d_in[13];
    const float* cp1_b      = (const float*)d_in[14];
    const float* cp2_w      = (const float*)d_in[15];
    const float* cp2_b      = (const float*)d_in[16];
    const float* cg_w       = (const float*)d_in[17];
    const float* cg_b       = (const float*)d_in[18];
    const float* gate_w     = (const float*)d_in[19];
    const float* gate_b     = (const float*)d_in[20];
    const float* fus_w      = (const float*)d_in[21];
    const float* fus_b      = (const float*)d_in[22];
    const float* ln_g       = (const float*)d_in[23];
    const float* ln_b       = (const float*)d_in[24];
    float* out = (float*)d_out;

    float *p_ring, *p_c2v, *p_h;
    __nv_bfloat16 *pA1h, *pA1l, *pA2h, *pA2l, *pB1h, *pB1l, *pB2h, *pB2l;
    cudaGetSymbolAddress((void**)&p_ring, g_ring);
    cudaGetSymbolAddress((void**)&p_c2v,  g_c2v);
    cudaGetSymbolAddress((void**)&p_h,    g_h);
    cudaGetSymbolAddress((void**)&pA1h, g_A1h);
    cudaGetSymbolAddress((void**)&pA1l, g_A1l);
    cudaGetSymbolAddress((void**)&pA2h, g_A2h);
    cudaGetSymbolAddress((void**)&pA2l, g_A2l);
    cudaGetSymbolAddress((void**)&pB1h, g_B1h);
    cudaGetSymbolAddress((void**)&pB1l, g_B1l);
    cudaGetSymbolAddress((void**)&pB2h, g_B2h);
    cudaGetSymbolAddress((void**)&pB2l, g_B2l);

    cudaFuncSetAttribute(k_mma<0>, cudaFuncAttributeMaxDynamicSharedMemorySize, SM_TOT);
    cudaFuncSetAttribute(k_mma<1>, cudaFuncAttributeMaxDynamicSharedMemorySize, SM_TOT);

    // mask path
    k_colstats<<<(LL*NNV+255)/256, 256>>>(x);
    k_sim<<<dim3(8,8,8), 256>>>();
    k_simred<<<NNV*NNV/256, 256>>>();
    k_topk<<<NNV/4, 128>>>();

    // router path
    k_partsums<<<BB*16, 256>>>(x);
    k_router<<<BB*NNV/256, 256>>>(var_embed, temp_w, temp_b, q_w, q_b, k_w, k_b, imp_w, imp_b);
    k_attn<<<BB*NNV/8, 256>>>();
    k_ring<<<dim3(2, LL/16, BB), 256>>>(x);

    // center path + weight prep
    k_cw<<<2, 256>>>(cluster_sc);
    k_prep<<<1, 256>>>(varproj_w, varproj_b, cp1_w, cp1_b, cp2_w, cp2_b);
    k_prepw<<<512, 128>>>(gate_w, gate_w + 512*512, pB1h, pB1l);
    k_prepw<<<512, 128>>>(fus_w, fus_w, pB2h, pB2l);
    k_ct<<<dim3(BB, 4), 256>>>(cg_w, cg_b);
    k_ctp<<<BB*16*64/256, 256>>>(cp1_w);
    k_xcs<<<BLV/16, 256>>>(x);
    k_scc2v<<<BLV, 128>>>();

    // tensor-core GEMMs (gate, then fuse) + LN
    k_mma<0><<<dim3(8, BLV/128), 256, SM_TOT>>>(pA1h, pA1l, pB1h, pB1l, gate_b,
                                                p_ring, p_c2v, pA2h, pA2l, nullptr);
    k_mma<1><<<dim3(8, BLV/128), 256, SM_TOT>>>(pA2h, pA2l, pB2h, pB2l, fus_b,
                                                x, nullptr, nullptr, nullptr, p_h);
    k_ln<<<BLV, 128>>>(ln_g, ln_b, out);

    (void)in_sizes; (void)n_in; (void)out_size;
}